// round 9
// baseline (speedup 1.0000x reference)
#include <cuda_runtime.h>
#include <cstdint>

// Problem constants (MemoryBank3: memory [1000,128,512] f32)
#define C_CLS   1000
#define N_SLOTS 128
#define D_DIM   512
#define S_B     4096
#define NEG_INF (-3.402823466e38f)

#define RING    12        // 2KB smem buffers per gather block
#define LEAD    8         // load issue distance ahead of stores

// Scratch (no device allocation allowed -> __device__ globals)
__device__ int   g_cls [S_B];            // argmax class per sample
__device__ float g_conf[S_B];            // float(batch_confidences[mask[s]])
__device__ int   g_fsrc[S_B];            // feature source row = mask[s]
__device__ int   g_slot[C_CLS * N_SLOTS];// final source pointer per output slot

// ---------------------------------------------------------------------------
__device__ __forceinline__ uint32_t smem_u32(const void* p) {
    uint32_t a;
    asm("{ .reg .u64 t; cvta.to.shared.u64 t, %1; cvt.u32.u64 %0, t; }"
        : "=r"(a) : "l"(p));
    return a;
}

// ---------------------------------------------------------------------------
// Warp-per-sample argmax, two-pass: (1) fmax tree of 1000 values,
// (2) min index equal to the max (first-occurrence semantics).
// mask/bconf dtype sniffed at runtime: selected_mask is arange(B), so as
// int32[] element 1 is 0 iff the buffer holds little-endian int64.
__global__ void __launch_bounds__(256) k_argmax(
        const float* __restrict__ tgt,
        const void* __restrict__ bconf,
        const void* __restrict__ mask) {
    int warp = (blockIdx.x * blockDim.x + threadIdx.x) >> 5;
    int lane = threadIdx.x & 31;

    const int* m32 = (const int*)mask;
    bool is64 = (m32[1] == 0);
    int m = is64 ? (int)((const long long*)mask)[warp] : m32[warp];

    const float4* row = (const float4*)(tgt + (size_t)m * C_CLS);
    float4 v[8];
#pragma unroll
    for (int it = 0; it < 8; it++) {
        int v4 = lane + 32 * it;
        v[it] = make_float4(NEG_INF, NEG_INF, NEG_INF, NEG_INF);
        if (v4 < 250) v[it] = __ldcs(row + v4);
    }
    float vm = NEG_INF;
#pragma unroll
    for (int it = 0; it < 8; it++)
        vm = fmaxf(vm, fmaxf(fmaxf(v[it].x, v[it].y), fmaxf(v[it].z, v[it].w)));
#pragma unroll
    for (int off = 16; off > 0; off >>= 1)
        vm = fmaxf(vm, __shfl_xor_sync(0xffffffffu, vm, off));
    int idx = 0x7fffffff;
#pragma unroll
    for (int it = 0; it < 8; it++) {
        int base = (lane + 32 * it) * 4;
        if (v[it].x == vm) idx = min(idx, base);
        if (v[it].y == vm) idx = min(idx, base + 1);
        if (v[it].z == vm) idx = min(idx, base + 2);
        if (v[it].w == vm) idx = min(idx, base + 3);
    }
#pragma unroll
    for (int off = 16; off > 0; off >>= 1)
        idx = min(idx, __shfl_xor_sync(0xffffffffu, idx, off));

    if (lane == 0) {
        g_cls [warp] = idx;
        g_conf[warp] = is64 ? (float)((const long long*)bconf)[m]
                            : (float)((const int*)bconf)[m];
        g_fsrc[warp] = m;
    }
}

// ---------------------------------------------------------------------------
// One warp per class (8 per block). g_cls staged into SMEM; warp scans it in
// order with ballots. First accepted update: general stable descending
// rank-sort; afterwards cfs is sorted so each update is a closed-form insert.
__global__ void __launch_bounds__(256) k_sim(const float* __restrict__ confid) {
    __shared__ int   scls[S_B];              // 16 KB staged class ids
    __shared__ float cf [8][N_SLOTS];
    __shared__ int   ptr[8][N_SLOTS];
    int w = threadIdx.x >> 5, lane = threadIdx.x & 31;
    int c = blockIdx.x * 8 + w;              // grid sized so c < C_CLS always
    float* cfs = cf[w];
    int*   ps  = ptr[w];

    for (int i = threadIdx.x; i < S_B; i += 256)
        scls[i] = g_cls[i];
#pragma unroll
    for (int q = 0; q < 4; q++) {
        int j = lane + 32 * q;
        cfs[j] = confid[c * N_SLOTS + j];
        ps[j]  = j;                          // initially: original memory row j
    }
    __syncthreads();

    bool sorted = false;                     // cfs sorted desc after 1st update
    for (int base = 0; base < S_B; base += 32) {
        unsigned msk = __ballot_sync(0xffffffffu, scls[base + lane] == c);
        while (msk) {
            int l = __ffs(msk) - 1;
            msk &= msk - 1;
            int   s    = base + l;
            float conf = g_conf[s];          // broadcast load
            if (!(conf > cfs[N_SLOTS - 1])) continue;   // cond = conf > rcf[-1]
            int fslot = N_SLOTS + g_fsrc[s];

            if (sorted) {
                int p = 0;
#pragma unroll
                for (int q = 0; q < 4; q++) {
                    int j = lane + 32 * q;
                    unsigned b = __ballot_sync(0xffffffffu,
                                               j < N_SLOTS - 1 && cfs[j] >= conf);
                    p += __popc(b);
                }
                float key[4]; int val[4];
#pragma unroll
                for (int q = 0; q < 4; q++) {
                    int j = lane + 32 * q;
                    key[q] = (j < p) ? cfs[j]    : (j == p ? conf  : cfs[j - 1]);
                    val[q] = (j < p) ? ps[j + 1] : (j == p ? fslot : ps[j]);
                }
                __syncwarp();
#pragma unroll
                for (int q = 0; q < 4; q++) {
                    int j = lane + 32 * q;
                    cfs[j] = key[q]; ps[j] = val[q];
                }
                __syncwarp();
            } else {
                float key[4]; int val[4]; int rk[4];
#pragma unroll
                for (int q = 0; q < 4; q++) {
                    int j = lane + 32 * q;
                    key[q] = (j < N_SLOTS - 1) ? cfs[j] : conf;   // unshifted cf
                    val[q] = (j < N_SLOTS - 1) ? ps[j + 1] : fslot; // shifted mem
                    rk[q]  = 0;
                }
                for (int k = 0; k < N_SLOTS; k++) {
                    float kk = (k < N_SLOTS - 1) ? cfs[k] : conf;
#pragma unroll
                    for (int q = 0; q < 4; q++) {
                        int j = lane + 32 * q;
                        rk[q] += (kk > key[q]) || (kk == key[q] && k < j);
                    }
                }
                __syncwarp();
#pragma unroll
                for (int q = 0; q < 4; q++) { cfs[rk[q]] = key[q]; ps[rk[q]] = val[q]; }
                __syncwarp();
                sorted = true;
            }
        }
    }
#pragma unroll
    for (int q = 0; q < 4; q++) {
        int j = lane + 32 * q;
        g_slot[c * N_SLOTS + j] = ps[j];
    }
}

// ---------------------------------------------------------------------------
// TMA bulk-copy gather: one block (1 warp) per class. Thread 0 drives a
// 12-buffer ring: cp.async.bulk G2S (mbarrier/expect_tx) issued LEAD=8 rows
// ahead of cp.async.bulk S2G (bulk_group). wait_group.read 3 before reusing
// a buffer guarantees its prior store drained (load r reuses row r-12's
// buffer; <=3 pending => stores <= r-11 complete).
__global__ void __launch_bounds__(32) k_gather_tma(
        const float* __restrict__ mem,
        const float* __restrict__ feats,
        float* __restrict__ out) {
    __shared__ __align__(1024) unsigned char s_buf[RING * 2048];
    __shared__ __align__(8)    unsigned long long s_mbar[RING];
    __shared__ int sps[N_SLOTS];
    int c = blockIdx.x, lane = threadIdx.x;

#pragma unroll
    for (int q = 0; q < 4; q++)
        sps[lane + 32 * q] = g_slot[c * N_SLOTS + lane + 32 * q];
    __syncwarp();
    if (lane != 0) return;

    uint32_t mb  = smem_u32(s_mbar);
    uint32_t buf = smem_u32(s_buf);
#pragma unroll
    for (int b = 0; b < RING; b++)
        asm volatile("mbarrier.init.shared.b64 [%0], %1;"
                     :: "r"(mb + 8 * b), "r"(1) : "memory");
    asm volatile("fence.proxy.async.shared::cta;" ::: "memory");

    const size_t obase = (size_t)c * N_SLOTS * D_DIM;

    auto issue_load = [&](int r) {
        int src = sps[r];
        const float* gp = (src < N_SLOTS)
            ? mem   + ((size_t)(c * N_SLOTS + src)) * D_DIM
            : feats + ((size_t)(src - N_SLOTS))     * D_DIM;
        uint32_t d = buf + (uint32_t)(r % RING) * 2048u;
        uint32_t m = mb + 8u * (uint32_t)(r % RING);
        asm volatile("mbarrier.arrive.expect_tx.shared.b64 _, [%0], %1;"
                     :: "r"(m), "r"(2048) : "memory");
        asm volatile(
            "cp.async.bulk.shared::cluster.global.mbarrier::complete_tx::bytes "
            "[%0], [%1], %2, [%3];"
            :: "r"(d), "l"(gp), "r"(2048), "r"(m) : "memory");
    };

#pragma unroll
    for (int r = 0; r < LEAD; r++) issue_load(r);

    for (int s = 0; s < N_SLOTS; s++) {
        uint32_t m = mb + 8u * (uint32_t)(s % RING);
        uint32_t parity = (uint32_t)((s / RING) & 1);
        // wait for load s to land
        unsigned done;
        do {
            asm volatile(
                "{ .reg .pred p; "
                "mbarrier.try_wait.parity.shared::cta.b64 p, [%1], %2; "
                "selp.b32 %0, 1, 0, p; }"
                : "=r"(done) : "r"(m), "r"(parity) : "memory");
        } while (!done);
        // store row s
        const float* dp = out + obase + (size_t)s * D_DIM;
        uint32_t sb = buf + (uint32_t)(s % RING) * 2048u;
        asm volatile("cp.async.bulk.global.shared::cta.bulk_group [%0], [%1], %2;"
                     :: "l"(dp), "r"(sb), "r"(2048) : "memory");
        asm volatile("cp.async.bulk.commit_group;" ::: "memory");
        int r = s + LEAD;
        if (r < N_SLOTS) {
            asm volatile("cp.async.bulk.wait_group.read 3;" ::: "memory");
            issue_load(r);
        }
    }
    asm volatile("cp.async.bulk.wait_group 0;" ::: "memory");
}

// ---------------------------------------------------------------------------
extern "C" void kernel_launch(void* const* d_in, const int* in_sizes, int n_in,
                              void* d_out, int out_size) {
    const float* memory = (const float*)d_in[0];
    const float* confid = (const float*)d_in[1];
    const float* feats  = (const float*)d_in[2];
    const float* tgts   = (const float*)d_in[3];
    const void*  bconf  = d_in[4];
    const void*  mask   = d_in[5];

    k_argmax    <<<S_B / 8, 256>>>(tgts, bconf, mask);   // warp per sample
    k_sim       <<<C_CLS / 8, 256>>>(confid);
    k_gather_tma<<<C_CLS, 32>>>(memory, feats, (float*)d_out);
}

// round 10
// speedup vs baseline: 1.0981x; 1.0981x over previous
#include <cuda_runtime.h>

// Problem constants (MemoryBank3: memory [1000,128,512] f32)
#define C_CLS   1000
#define N_SLOTS 128
#define D_DIM   512
#define S_B     4096

// Scratch (no device allocation allowed -> __device__ globals)
__device__ int   g_cls [S_B];            // argmax class per sample
__device__ float g_conf[S_B];            // float(batch_confidences[mask[s]])
__device__ int   g_fsrc[S_B];            // feature source row = mask[s]
__device__ int   g_slot[C_CLS * N_SLOTS];// final source pointer per output slot

// ---------------------------------------------------------------------------
// Warp-per-sample argmax (predicated compare chain — fastest measured form).
// mask/bconf dtype sniffed at runtime: selected_mask is arange(B), so as
// int32[] element 1 is 0 iff the buffer holds little-endian int64.
__global__ void __launch_bounds__(256) k_argmax(
        const float* __restrict__ tgt,
        const void* __restrict__ bconf,
        const void* __restrict__ mask) {
    int warp = (blockIdx.x * blockDim.x + threadIdx.x) >> 5;
    int lane = threadIdx.x & 31;

    const int* m32 = (const int*)mask;
    bool is64 = (m32[1] == 0);
    int m = is64 ? (int)((const long long*)mask)[warp] : m32[warp];

    const float4* row = (const float4*)(tgt + (size_t)m * C_CLS);
    float best = -3.402823466e38f;
    int   bidx = C_CLS;
#pragma unroll
    for (int it = 0; it < 8; it++) {
        int v4 = lane + 32 * it;             // float4 index, ascending per lane
        if (v4 < 250) {
            float4 v = __ldcs(row + v4);
            int base = v4 * 4;
            if (v.x > best) { best = v.x; bidx = base;     }
            if (v.y > best) { best = v.y; bidx = base + 1; }
            if (v.z > best) { best = v.z; bidx = base + 2; }
            if (v.w > best) { best = v.w; bidx = base + 3; }
        }
    }
    // warp reduce: larger value wins; tie -> lower index (first occurrence)
#pragma unroll
    for (int off = 16; off > 0; off >>= 1) {
        float ov = __shfl_down_sync(0xffffffffu, best, off);
        int   oi = __shfl_down_sync(0xffffffffu, bidx, off);
        if (ov > best || (ov == best && oi < bidx)) { best = ov; bidx = oi; }
    }
    if (lane == 0) {
        g_cls [warp] = bidx;
        g_conf[warp] = is64 ? (float)((const long long*)bconf)[m]
                            : (float)((const int*)bconf)[m];
        g_fsrc[warp] = m;
    }
}

// ---------------------------------------------------------------------------
// One warp per class (8 per block). g_cls staged into SMEM; warp scans it in
// order with ballots. First accepted update: general stable descending
// rank-sort; afterwards cfs is sorted so each update is a closed-form insert.
__global__ void __launch_bounds__(256) k_sim(const float* __restrict__ confid) {
    __shared__ int   scls[S_B];              // 16 KB staged class ids
    __shared__ float cf [8][N_SLOTS];
    __shared__ int   ptr[8][N_SLOTS];
    int w = threadIdx.x >> 5, lane = threadIdx.x & 31;
    int c = blockIdx.x * 8 + w;              // grid sized so c < C_CLS always
    float* cfs = cf[w];
    int*   ps  = ptr[w];

    for (int i = threadIdx.x; i < S_B; i += 256)
        scls[i] = g_cls[i];
#pragma unroll
    for (int q = 0; q < 4; q++) {
        int j = lane + 32 * q;
        cfs[j] = confid[c * N_SLOTS + j];
        ps[j]  = j;                          // initially: original memory row j
    }
    __syncthreads();

    bool sorted = false;                     // cfs sorted desc after 1st update
    for (int base = 0; base < S_B; base += 32) {
        unsigned msk = __ballot_sync(0xffffffffu, scls[base + lane] == c);
        while (msk) {
            int l = __ffs(msk) - 1;
            msk &= msk - 1;
            int   s    = base + l;
            float conf = g_conf[s];          // broadcast load
            if (!(conf > cfs[N_SLOTS - 1])) continue;   // cond = conf > rcf[-1]
            int fslot = N_SLOTS + g_fsrc[s];

            if (sorted) {
                // insertion: p = #{j<N-1 : cfs[j] >= conf} (ties precede)
                int p = 0;
#pragma unroll
                for (int q = 0; q < 4; q++) {
                    int j = lane + 32 * q;
                    unsigned b = __ballot_sync(0xffffffffu,
                                               j < N_SLOTS - 1 && cfs[j] >= conf);
                    p += __popc(b);
                }
                float key[4]; int val[4];
#pragma unroll
                for (int q = 0; q < 4; q++) {
                    int j = lane + 32 * q;
                    key[q] = (j < p) ? cfs[j]    : (j == p ? conf  : cfs[j - 1]);
                    val[q] = (j < p) ? ps[j + 1] : (j == p ? fslot : ps[j]);
                }
                __syncwarp();
#pragma unroll
                for (int q = 0; q < 4; q++) {
                    int j = lane + 32 * q;
                    cfs[j] = key[q]; ps[j] = val[q];
                }
                __syncwarp();
            } else {
                // general stable descending rank-sort (unsorted initial state)
                float key[4]; int val[4]; int rk[4];
#pragma unroll
                for (int q = 0; q < 4; q++) {
                    int j = lane + 32 * q;
                    key[q] = (j < N_SLOTS - 1) ? cfs[j] : conf;     // unshifted cf
                    val[q] = (j < N_SLOTS - 1) ? ps[j + 1] : fslot; // shifted mem
                    rk[q]  = 0;
                }
                for (int k = 0; k < N_SLOTS; k++) {
                    float kk = (k < N_SLOTS - 1) ? cfs[k] : conf;
#pragma unroll
                    for (int q = 0; q < 4; q++) {
                        int j = lane + 32 * q;
                        rk[q] += (kk > key[q]) || (kk == key[q] && k < j);
                    }
                }
                __syncwarp();
#pragma unroll
                for (int q = 0; q < 4; q++) { cfs[rk[q]] = key[q]; ps[rk[q]] = val[q]; }
                __syncwarp();
                sorted = true;
            }
        }
    }
#pragma unroll
    for (int q = 0; q < 4; q++) {
        int j = lane + 32 * q;
        g_slot[c * N_SLOTS + j] = ps[j];
    }
}

// ---------------------------------------------------------------------------
// Four slots per warp: 16 independent LDG.128 front-batched before any store
// (MLP 16/thread), evict-first streaming both directions.
__global__ void __launch_bounds__(256) k_gather(
        const float* __restrict__ mem,
        const float* __restrict__ feats,
        float* __restrict__ out) {
    int warp = blockIdx.x * 8 + (threadIdx.x >> 5);
    int lane = threadIdx.x & 31;
    int s0   = warp * 4;

    const float4* sp[4];
    float4* dp[4];
#pragma unroll
    for (int r = 0; r < 4; r++) {
        int slot = s0 + r;
        int src  = g_slot[slot];
        int c    = slot >> 7;
        sp[r] = (src < N_SLOTS)
            ? (const float4*)(mem   + ((size_t)(c * N_SLOTS + src)) * D_DIM)
            : (const float4*)(feats + ((size_t)(src - N_SLOTS))     * D_DIM);
        dp[r] = (float4*)(out + (size_t)slot * D_DIM);
    }

    float4 v[4][4];
#pragma unroll
    for (int r = 0; r < 4; r++) {
#pragma unroll
        for (int q = 0; q < 4; q++)
            v[r][q] = __ldcs(sp[r] + lane + 32 * q);
    }
#pragma unroll
    for (int r = 0; r < 4; r++) {
#pragma unroll
        for (int q = 0; q < 4; q++)
            __stcs(dp[r] + lane + 32 * q, v[r][q]);
    }
}

// ---------------------------------------------------------------------------
extern "C" void kernel_launch(void* const* d_in, const int* in_sizes, int n_in,
                              void* d_out, int out_size) {
    const float* memory = (const float*)d_in[0];
    const float* confid = (const float*)d_in[1];
    const float* feats  = (const float*)d_in[2];
    const float* tgts   = (const float*)d_in[3];
    const void*  bconf  = d_in[4];
    const void*  mask   = d_in[5];

    k_argmax <<<S_B / 8, 256>>>(tgts, bconf, mask);           // warp per sample
    k_sim    <<<C_CLS / 8, 256>>>(confid);
    k_gather <<<C_CLS * N_SLOTS / 32, 256>>>(memory, feats, (float*)d_out);
}